// round 8
// baseline (speedup 1.0000x reference)
#include <cuda_runtime.h>

// Problem constants (from reference: B=32, T=512, F=513, S=3)
#define BB     32
#define NPB    262656          // T*F triples per batch
#define NCHUNK (NPB / 4)       // 65664 chunks of 4 triples (12 floats) per batch
#define BLKX   13              // blocks per batch -> 416 CTAs (<=444 slots @3/SM: single wave)
#define NTHR   256
#define NBLK   (BB * BLKX)     // 416

typedef unsigned long long u64;

// Cost-matrix accumulators + hierarchical completion counters.
// Zero at static init; finisher re-zeroes everything -> graph-replay safe.
__device__ float g_C[BB * 9];
__device__ unsigned int g_cnt_b[BB];
__device__ unsigned int g_cnt;

__device__ __forceinline__ u64 pack2(float lo, float hi) {
    u64 r; asm("mov.b64 %0, {%1, %2};" : "=l"(r) : "f"(lo), "f"(hi)); return r;
}
__device__ __forceinline__ void unpack2(float& lo, float& hi, u64 a) {
    asm("mov.b64 {%0, %1}, %2;" : "=f"(lo), "=f"(hi) : "l"(a));
}
__device__ __forceinline__ u64 sub2(u64 a, u64 b) {
    u64 r; asm("sub.rn.f32x2 %0, %1, %2;" : "=l"(r) : "l"(a), "l"(b)); return r;
}
__device__ __forceinline__ u64 add2(u64 a, u64 b) {
    u64 r; asm("add.rn.f32x2 %0, %1, %2;" : "=l"(r) : "l"(a), "l"(b)); return r;
}
__device__ __forceinline__ u64 abs2(u64 a) {
    return a & 0x7FFFFFFF7FFFFFFFULL;
}

// Accumulate one 12-float chunk (3 float4 per array) into acc[9].
__device__ __forceinline__ void accum_chunk(
    u64* acc,
    const float4 e0, const float4 e1, const float4 e2,
    const float4 t0, const float4 t1, const float4 t2)
{
    // Pair A = (n0, n1):  n0=(e0.x,e0.y,e0.z)  n1=(e0.w,e1.x,e1.y)
    const u64 EA0 = pack2(e0.x, e0.w), EA1 = pack2(e0.y, e1.x), EA2 = pack2(e0.z, e1.y);
    const u64 TA0 = pack2(t0.x, t0.w), TA1 = pack2(t0.y, t1.x), TA2 = pack2(t0.z, t1.y);
    // Pair B = (n2, n3):  n2=(e1.z,e1.w,e2.x)  n3=(e2.y,e2.z,e2.w)
    const u64 EB0 = pack2(e1.z, e2.y), EB1 = pack2(e1.w, e2.z), EB2 = pack2(e2.x, e2.w);
    const u64 TB0 = pack2(t1.z, t2.y), TB1 = pack2(t1.w, t2.z), TB2 = pack2(t2.x, t2.w);

    acc[0] = add2(acc[0], abs2(sub2(EA0, TA0)));
    acc[1] = add2(acc[1], abs2(sub2(EA0, TA1)));
    acc[2] = add2(acc[2], abs2(sub2(EA0, TA2)));
    acc[3] = add2(acc[3], abs2(sub2(EA1, TA0)));
    acc[4] = add2(acc[4], abs2(sub2(EA1, TA1)));
    acc[5] = add2(acc[5], abs2(sub2(EA1, TA2)));
    acc[6] = add2(acc[6], abs2(sub2(EA2, TA0)));
    acc[7] = add2(acc[7], abs2(sub2(EA2, TA1)));
    acc[8] = add2(acc[8], abs2(sub2(EA2, TA2)));

    acc[0] = add2(acc[0], abs2(sub2(EB0, TB0)));
    acc[1] = add2(acc[1], abs2(sub2(EB0, TB1)));
    acc[2] = add2(acc[2], abs2(sub2(EB0, TB2)));
    acc[3] = add2(acc[3], abs2(sub2(EB1, TB0)));
    acc[4] = add2(acc[4], abs2(sub2(EB1, TB1)));
    acc[5] = add2(acc[5], abs2(sub2(EB1, TB2)));
    acc[6] = add2(acc[6], abs2(sub2(EB2, TB0)));
    acc[7] = add2(acc[7], abs2(sub2(EB2, TB1)));
    acc[8] = add2(acc[8], abs2(sub2(EB2, TB2)));
}

// Fused kernel. grid (BLKX, BB), block NTHR.
__global__ void __launch_bounds__(NTHR) pil_fused_kernel(
    const float4* __restrict__ est, const float4* __restrict__ tgt,
    float* __restrict__ out)
{
    const int b = blockIdx.y;
    const float4* __restrict__ e = est + (size_t)b * (NPB * 3 / 4);
    const float4* __restrict__ t = tgt + (size_t)b * (NPB * 3 / 4);

    u64 acc[9];
#pragma unroll
    for (int k = 0; k < 9; k++) acc[k] = 0ULL;

    const int stride = BLKX * NTHR;   // 3328 threads per batch
    int k = blockIdx.x * NTHR + threadIdx.x;

    // Main loop: two chunks per iteration, ALL 12 LDG.128 front-batched
    // (streaming loads: data is single-use, evict-first).
    for (; k + stride < NCHUNK; k += 2 * stride) {
        const int k2 = k + stride;
        const float4 ea0 = __ldcs(&e[3 * k + 0]);
        const float4 ea1 = __ldcs(&e[3 * k + 1]);
        const float4 ea2 = __ldcs(&e[3 * k + 2]);
        const float4 ta0 = __ldcs(&t[3 * k + 0]);
        const float4 ta1 = __ldcs(&t[3 * k + 1]);
        const float4 ta2 = __ldcs(&t[3 * k + 2]);
        const float4 eb0 = __ldcs(&e[3 * k2 + 0]);
        const float4 eb1 = __ldcs(&e[3 * k2 + 1]);
        const float4 eb2 = __ldcs(&e[3 * k2 + 2]);
        const float4 tb0 = __ldcs(&t[3 * k2 + 0]);
        const float4 tb1 = __ldcs(&t[3 * k2 + 1]);
        const float4 tb2 = __ldcs(&t[3 * k2 + 2]);

        accum_chunk(acc, ea0, ea1, ea2, ta0, ta1, ta2);
        accum_chunk(acc, eb0, eb1, eb2, tb0, tb1, tb2);
    }
    // Tail: single chunks.
    for (; k < NCHUNK; k += stride) {
        const float4 e0 = __ldcs(&e[3 * k + 0]);
        const float4 e1 = __ldcs(&e[3 * k + 1]);
        const float4 e2 = __ldcs(&e[3 * k + 2]);
        const float4 t0 = __ldcs(&t[3 * k + 0]);
        const float4 t1 = __ldcs(&t[3 * k + 1]);
        const float4 t2 = __ldcs(&t[3 * k + 2]);
        accum_chunk(acc, e0, e1, e2, t0, t1, t2);
    }

    // Collapse packed halves.
    float a[9];
#pragma unroll
    for (int q = 0; q < 9; q++) {
        float lo, hi;
        unpack2(lo, hi, acc[q]);
        a[q] = lo + hi;
    }

    // Warp reduction.
#pragma unroll
    for (int off = 16; off > 0; off >>= 1) {
#pragma unroll
        for (int q = 0; q < 9; q++)
            a[q] += __shfl_down_sync(0xFFFFFFFFu, a[q], off);
    }

    // Block reduction across 8 warps.
    __shared__ float s_part[NTHR / 32][9];
    const int lane = threadIdx.x & 31;
    const int warp = threadIdx.x >> 5;
    if (lane == 0) {
#pragma unroll
        for (int q = 0; q < 9; q++) s_part[warp][q] = a[q];
    }
    __syncthreads();

    if (threadIdx.x < 9) {
        float s = 0.0f;
#pragma unroll
        for (int w = 0; w < NTHR / 32; w++) s += s_part[w][threadIdx.x];
        atomicAdd(&g_C[b * 9 + threadIdx.x], s);   // 288 spread addresses
    }

    // ---- hierarchical last-block-done ----
    __shared__ unsigned int s_islast;
    __threadfence();
    if (threadIdx.x == 0) {
        s_islast = 0;
        if (atomicAdd(&g_cnt_b[b], 1u) == BLKX - 1) {
            __threadfence();
            s_islast = (atomicAdd(&g_cnt, 1u) == BB - 1);
        }
    }
    __syncthreads();
    if (!s_islast) return;

    // ---- finisher: permutation-min epilogue ----
    __shared__ float sC[BB * 9];
    const int tid = threadIdx.x;
    for (int ent = tid; ent < BB * 9; ent += NTHR)
        sC[ent] = __ldcg(&g_C[ent]) * (1.0f / (float)NPB);
    __syncthreads();

    if (tid < 32) {
        const float* c = &sC[tid * 9];
        float best = c[0] + c[4] + c[8];
        best = fminf(best, c[0] + c[7] + c[5]);
        best = fminf(best, c[3] + c[1] + c[8]);
        best = fminf(best, c[3] + c[7] + c[2]);
        best = fminf(best, c[6] + c[1] + c[5]);
        best = fminf(best, c[6] + c[4] + c[2]);
        best *= (1.0f / 3.0f);

#pragma unroll
        for (int off = 16; off > 0; off >>= 1)
            best += __shfl_down_sync(0xFFFFFFFFu, best, off);

        if (tid == 0) out[0] = best * (1.0f / (float)BB);
    }
    __syncthreads();

    for (int ent = tid; ent < BB * 9; ent += NTHR) g_C[ent] = 0.0f;
    if (tid < BB) g_cnt_b[tid] = 0u;
    if (tid == 0) g_cnt = 0u;
}

extern "C" void kernel_launch(void* const* d_in, const int* in_sizes, int n_in,
                              void* d_out, int out_size) {
    const float4* est = (const float4*)d_in[0];
    const float4* tgt = (const float4*)d_in[1];
    float* out = (float*)d_out;

    dim3 grid(BLKX, BB);
    pil_fused_kernel<<<grid, NTHR>>>(est, tgt, out);
}

// round 11
// speedup vs baseline: 1.0057x; 1.0057x over previous
#include <cuda_runtime.h>

// Problem constants (from reference: B=32, T=512, F=513, S=3)
#define BB     32
#define NPB    262656          // T*F triples per batch
#define NCHUNK (NPB / 4)       // 65664 chunks of 4 triples (12 floats) per batch
#define NTHR   256
#define NBLK   444             // 148 SMs x 3 CTAs/SM: one perfectly-balanced wave
// Batches 0..27 get 14 blocks, batches 28..31 get 13 (28*14 + 4*13 = 444).
#define SPLIT_ID   392         // 28*14
#define SPLIT_B    28

typedef unsigned long long u64;

// Cost-matrix accumulators + hierarchical completion counters.
// Zero at static init; finisher re-zeroes everything -> graph-replay safe.
__device__ float g_C[BB * 9];
__device__ unsigned int g_cnt_b[BB];
__device__ unsigned int g_cnt;

__device__ __forceinline__ u64 pack2(float lo, float hi) {
    u64 r; asm("mov.b64 %0, {%1, %2};" : "=l"(r) : "f"(lo), "f"(hi)); return r;
}
__device__ __forceinline__ void unpack2(float& lo, float& hi, u64 a) {
    asm("mov.b64 {%0, %1}, %2;" : "=f"(lo), "=f"(hi) : "l"(a));
}
__device__ __forceinline__ u64 sub2(u64 a, u64 b) {
    u64 r; asm("sub.rn.f32x2 %0, %1, %2;" : "=l"(r) : "l"(a), "l"(b)); return r;
}
__device__ __forceinline__ u64 add2(u64 a, u64 b) {
    u64 r; asm("add.rn.f32x2 %0, %1, %2;" : "=l"(r) : "l"(a), "l"(b)); return r;
}
__device__ __forceinline__ u64 abs2(u64 a) {
    return a & 0x7FFFFFFF7FFFFFFFULL;
}

// Accumulate one 12-float chunk (3 float4 per array) into acc[9].
__device__ __forceinline__ void accum_chunk(
    u64* acc,
    const float4 e0, const float4 e1, const float4 e2,
    const float4 t0, const float4 t1, const float4 t2)
{
    // Pair A = (n0, n1):  n0=(e0.x,e0.y,e0.z)  n1=(e0.w,e1.x,e1.y)
    const u64 EA0 = pack2(e0.x, e0.w), EA1 = pack2(e0.y, e1.x), EA2 = pack2(e0.z, e1.y);
    const u64 TA0 = pack2(t0.x, t0.w), TA1 = pack2(t0.y, t1.x), TA2 = pack2(t0.z, t1.y);
    // Pair B = (n2, n3):  n2=(e1.z,e1.w,e2.x)  n3=(e2.y,e2.z,e2.w)
    const u64 EB0 = pack2(e1.z, e2.y), EB1 = pack2(e1.w, e2.z), EB2 = pack2(e2.x, e2.w);
    const u64 TB0 = pack2(t1.z, t2.y), TB1 = pack2(t1.w, t2.z), TB2 = pack2(t2.x, t2.w);

    acc[0] = add2(acc[0], abs2(sub2(EA0, TA0)));
    acc[1] = add2(acc[1], abs2(sub2(EA0, TA1)));
    acc[2] = add2(acc[2], abs2(sub2(EA0, TA2)));
    acc[3] = add2(acc[3], abs2(sub2(EA1, TA0)));
    acc[4] = add2(acc[4], abs2(sub2(EA1, TA1)));
    acc[5] = add2(acc[5], abs2(sub2(EA1, TA2)));
    acc[6] = add2(acc[6], abs2(sub2(EA2, TA0)));
    acc[7] = add2(acc[7], abs2(sub2(EA2, TA1)));
    acc[8] = add2(acc[8], abs2(sub2(EA2, TA2)));

    acc[0] = add2(acc[0], abs2(sub2(EB0, TB0)));
    acc[1] = add2(acc[1], abs2(sub2(EB0, TB1)));
    acc[2] = add2(acc[2], abs2(sub2(EB0, TB2)));
    acc[3] = add2(acc[3], abs2(sub2(EB1, TB0)));
    acc[4] = add2(acc[4], abs2(sub2(EB1, TB1)));
    acc[5] = add2(acc[5], abs2(sub2(EB1, TB2)));
    acc[6] = add2(acc[6], abs2(sub2(EB2, TB0)));
    acc[7] = add2(acc[7], abs2(sub2(EB2, TB1)));
    acc[8] = add2(acc[8], abs2(sub2(EB2, TB2)));
}

// Fused kernel. 1D grid of NBLK CTAs; uneven blocks-per-batch for perfect wave balance.
__global__ void __launch_bounds__(NTHR) pil_fused_kernel(
    const float4* __restrict__ est, const float4* __restrict__ tgt,
    float* __restrict__ out)
{
    // Map flat block id -> (batch b, block-in-batch x, blocks-in-batch nb).
    int b, x, nb;
    {
        const int id = blockIdx.x;
        if (id < SPLIT_ID) { b = id / 14;           x = id % 14;           nb = 14; }
        else               { b = SPLIT_B + (id - SPLIT_ID) / 13;
                             x = (id - SPLIT_ID) % 13;                     nb = 13; }
    }

    const float4* __restrict__ e = est + (size_t)b * (NPB * 3 / 4);
    const float4* __restrict__ t = tgt + (size_t)b * (NPB * 3 / 4);

    u64 acc[9];
#pragma unroll
    for (int q = 0; q < 9; q++) acc[q] = 0ULL;

    const int stride = nb * NTHR;
    int k = x * NTHR + threadIdx.x;

    // Main loop: two chunks per iteration, all 12 LDG.128 front-batched;
    // streaming loads (single-use data, evict-first).
    for (; k + stride < NCHUNK; k += 2 * stride) {
        const int k2 = k + stride;
        const float4 ea0 = __ldcs(&e[3 * k + 0]);
        const float4 ea1 = __ldcs(&e[3 * k + 1]);
        const float4 ea2 = __ldcs(&e[3 * k + 2]);
        const float4 ta0 = __ldcs(&t[3 * k + 0]);
        const float4 ta1 = __ldcs(&t[3 * k + 1]);
        const float4 ta2 = __ldcs(&t[3 * k + 2]);
        const float4 eb0 = __ldcs(&e[3 * k2 + 0]);
        const float4 eb1 = __ldcs(&e[3 * k2 + 1]);
        const float4 eb2 = __ldcs(&e[3 * k2 + 2]);
        const float4 tb0 = __ldcs(&t[3 * k2 + 0]);
        const float4 tb1 = __ldcs(&t[3 * k2 + 1]);
        const float4 tb2 = __ldcs(&t[3 * k2 + 2]);

        accum_chunk(acc, ea0, ea1, ea2, ta0, ta1, ta2);
        accum_chunk(acc, eb0, eb1, eb2, tb0, tb1, tb2);
    }
    for (; k < NCHUNK; k += stride) {
        const float4 e0 = __ldcs(&e[3 * k + 0]);
        const float4 e1 = __ldcs(&e[3 * k + 1]);
        const float4 e2 = __ldcs(&e[3 * k + 2]);
        const float4 t0 = __ldcs(&t[3 * k + 0]);
        const float4 t1 = __ldcs(&t[3 * k + 1]);
        const float4 t2 = __ldcs(&t[3 * k + 2]);
        accum_chunk(acc, e0, e1, e2, t0, t1, t2);
    }

    // Collapse packed halves.
    float a[9];
#pragma unroll
    for (int q = 0; q < 9; q++) {
        float lo, hi;
        unpack2(lo, hi, acc[q]);
        a[q] = lo + hi;
    }

    // Warp reduction.
#pragma unroll
    for (int off = 16; off > 0; off >>= 1) {
#pragma unroll
        for (int q = 0; q < 9; q++)
            a[q] += __shfl_down_sync(0xFFFFFFFFu, a[q], off);
    }

    // Block reduction across 8 warps.
    __shared__ float s_part[NTHR / 32][9];
    const int lane = threadIdx.x & 31;
    const int warp = threadIdx.x >> 5;
    if (lane == 0) {
#pragma unroll
        for (int q = 0; q < 9; q++) s_part[warp][q] = a[q];
    }
    __syncthreads();

    if (threadIdx.x < 9) {
        float s = 0.0f;
#pragma unroll
        for (int w = 0; w < NTHR / 32; w++) s += s_part[w][threadIdx.x];
        atomicAdd(&g_C[b * 9 + threadIdx.x], s);   // 288 spread addresses
    }

    // ---- hierarchical last-block-done ----
    __shared__ unsigned int s_islast;
    __threadfence();
    if (threadIdx.x == 0) {
        s_islast = 0;
        if (atomicAdd(&g_cnt_b[b], 1u) == (unsigned)(nb - 1)) {   // last block of batch b
            __threadfence();
            s_islast = (atomicAdd(&g_cnt, 1u) == BB - 1);          // last batch overall
        }
    }
    __syncthreads();
    if (!s_islast) return;

    // ---- finisher: permutation-min epilogue ----
    __shared__ float sC[BB * 9];
    const int tid = threadIdx.x;
    for (int ent = tid; ent < BB * 9; ent += NTHR)
        sC[ent] = __ldcg(&g_C[ent]) * (1.0f / (float)NPB);
    __syncthreads();

    if (tid < 32) {
        const float* c = &sC[tid * 9];
        // C[i][j] = c[i*3+j]; loss_p = (C[p0][0] + C[p1][1] + C[p2][2]) / 3
        float best = c[0] + c[4] + c[8];
        best = fminf(best, c[0] + c[7] + c[5]);
        best = fminf(best, c[3] + c[1] + c[8]);
        best = fminf(best, c[3] + c[7] + c[2]);
        best = fminf(best, c[6] + c[1] + c[5]);
        best = fminf(best, c[6] + c[4] + c[2]);
        best *= (1.0f / 3.0f);

#pragma unroll
        for (int off = 16; off > 0; off >>= 1)
            best += __shfl_down_sync(0xFFFFFFFFu, best, off);

        if (tid == 0) out[0] = best * (1.0f / (float)BB);
    }
    __syncthreads();

    // Reset ALL scratch for the next graph replay.
    for (int ent = tid; ent < BB * 9; ent += NTHR) g_C[ent] = 0.0f;
    if (tid < BB) g_cnt_b[tid] = 0u;
    if (tid == 0) g_cnt = 0u;
}

extern "C" void kernel_launch(void* const* d_in, const int* in_sizes, int n_in,
                              void* d_out, int out_size) {
    const float4* est = (const float4*)d_in[0];
    const float4* tgt = (const float4*)d_in[1];
    float* out = (float*)d_out;

    pil_fused_kernel<<<NBLK, NTHR>>>(est, tgt, out);
}

// round 12
// speedup vs baseline: 1.0608x; 1.0548x over previous
#include <cuda_runtime.h>
#include <cstdint>

// Problem constants (B=32, T=512, F=513, S=3)
#define BB        32
#define NPB       262656            // triples per batch
#define NQUADS    65664             // NPB/4: quads (4 triples = 48B) per batch
#define BLKX      16                // blocks per batch
#define NBLK      (BB * BLKX)       // 512 CTAs
#define NTHR      256
#define QPB       (NQUADS / BLKX)   // 4104 quads per block
#define QPS       216               // quads per stage
#define NSTAGES   (QPB / QPS)       // 19, exact
#define STAGE_B   (QPS * 48)        // 10368 bytes per array per stage
#define STAGE_F4  (QPS * 3)         // 648 float4 per array per stage

typedef unsigned long long u64;

// Cost-matrix accumulators + hierarchical completion counters.
// Zero at static init; finisher re-zeroes everything -> graph-replay safe.
__device__ float g_C[BB * 9];
__device__ unsigned int g_cnt_b[BB];
__device__ unsigned int g_cnt;

__device__ __forceinline__ uint32_t smem_u32(const void* p) {
    uint32_t a;
    asm("{ .reg .u64 t; cvta.to.shared.u64 t, %1; cvt.u32.u64 %0, t; }" : "=r"(a) : "l"(p));
    return a;
}
__device__ __forceinline__ u64 pack2(float lo, float hi) {
    u64 r; asm("mov.b64 %0, {%1, %2};" : "=l"(r) : "f"(lo), "f"(hi)); return r;
}
__device__ __forceinline__ void unpack2(float& lo, float& hi, u64 a) {
    asm("mov.b64 {%0, %1}, %2;" : "=f"(lo), "=f"(hi) : "l"(a));
}
__device__ __forceinline__ u64 sub2(u64 a, u64 b) {
    u64 r; asm("sub.rn.f32x2 %0, %1, %2;" : "=l"(r) : "l"(a), "l"(b)); return r;
}
__device__ __forceinline__ u64 add2(u64 a, u64 b) {
    u64 r; asm("add.rn.f32x2 %0, %1, %2;" : "=l"(r) : "l"(a), "l"(b)); return r;
}
__device__ __forceinline__ u64 abs2(u64 a) { return a & 0x7FFFFFFF7FFFFFFFULL; }

__device__ __forceinline__ void mbar_init(uint32_t mbar, uint32_t cnt) {
    asm volatile("mbarrier.init.shared.b64 [%0], %1;" :: "r"(mbar), "r"(cnt) : "memory");
}
__device__ __forceinline__ void mbar_expect_tx(uint32_t mbar, uint32_t bytes) {
    asm volatile("mbarrier.arrive.expect_tx.shared.b64 _, [%0], %1;"
                 :: "r"(mbar), "r"(bytes) : "memory");
}
__device__ __forceinline__ void tma_bulk_1d(uint32_t smem_dst, const void* gmem_src,
                                            uint32_t bytes, uint32_t mbar) {
    asm volatile("cp.async.bulk.shared::cluster.global.mbarrier::complete_tx::bytes "
                 "[%0], [%1], %2, [%3];"
                 :: "r"(smem_dst), "l"(gmem_src), "r"(bytes), "r"(mbar) : "memory");
}
__device__ __forceinline__ void mbar_wait(uint32_t mbar, uint32_t parity) {
    asm volatile(
        "{\n\t"
        ".reg .pred P;\n\t"
        "WAIT_%=:\n\t"
        "mbarrier.try_wait.parity.acquire.cta.shared::cta.b64 P, [%0], %1, 0x989680;\n\t"
        "@P bra.uni DONE_%=;\n\t"
        "bra.uni WAIT_%=;\n\t"
        "DONE_%=:\n\t"
        "}"
        :: "r"(mbar), "r"(parity) : "memory");
}

// Accumulate one 12-float quad (3 float4 per array) into acc[9].
__device__ __forceinline__ void accum_chunk(
    u64* acc,
    const float4 e0, const float4 e1, const float4 e2,
    const float4 t0, const float4 t1, const float4 t2)
{
    const u64 EA0 = pack2(e0.x, e0.w), EA1 = pack2(e0.y, e1.x), EA2 = pack2(e0.z, e1.y);
    const u64 TA0 = pack2(t0.x, t0.w), TA1 = pack2(t0.y, t1.x), TA2 = pack2(t0.z, t1.y);
    const u64 EB0 = pack2(e1.z, e2.y), EB1 = pack2(e1.w, e2.z), EB2 = pack2(e2.x, e2.w);
    const u64 TB0 = pack2(t1.z, t2.y), TB1 = pack2(t1.w, t2.z), TB2 = pack2(t2.x, t2.w);

    acc[0] = add2(acc[0], abs2(sub2(EA0, TA0)));
    acc[1] = add2(acc[1], abs2(sub2(EA0, TA1)));
    acc[2] = add2(acc[2], abs2(sub2(EA0, TA2)));
    acc[3] = add2(acc[3], abs2(sub2(EA1, TA0)));
    acc[4] = add2(acc[4], abs2(sub2(EA1, TA1)));
    acc[5] = add2(acc[5], abs2(sub2(EA1, TA2)));
    acc[6] = add2(acc[6], abs2(sub2(EA2, TA0)));
    acc[7] = add2(acc[7], abs2(sub2(EA2, TA1)));
    acc[8] = add2(acc[8], abs2(sub2(EA2, TA2)));

    acc[0] = add2(acc[0], abs2(sub2(EB0, TB0)));
    acc[1] = add2(acc[1], abs2(sub2(EB0, TB1)));
    acc[2] = add2(acc[2], abs2(sub2(EB0, TB2)));
    acc[3] = add2(acc[3], abs2(sub2(EB1, TB0)));
    acc[4] = add2(acc[4], abs2(sub2(EB1, TB1)));
    acc[5] = add2(acc[5], abs2(sub2(EB1, TB2)));
    acc[6] = add2(acc[6], abs2(sub2(EB2, TB0)));
    acc[7] = add2(acc[7], abs2(sub2(EB2, TB1)));
    acc[8] = add2(acc[8], abs2(sub2(EB2, TB2)));
}

__global__ void __launch_bounds__(NTHR) pil_tma_kernel(
    const float* __restrict__ est, const float* __restrict__ tgt,
    float* __restrict__ out)
{
    // Double-buffered SMEM tiles (TMA destination). 2 x (10368 + 10368) = 41472 B.
    __shared__ __align__(128) float4 s_e[2][STAGE_F4];
    __shared__ __align__(128) float4 s_t[2][STAGE_F4];
    __shared__ __align__(8) unsigned long long s_mbar[2];

    const int tid = threadIdx.x;
    const int b = blockIdx.x >> 4;        // batch
    const int x = blockIdx.x & 15;        // block-in-batch

    const uint32_t mb0 = smem_u32(&s_mbar[0]);
    const uint32_t mb1 = smem_u32(&s_mbar[1]);
    const uint32_t se0 = smem_u32(&s_e[0][0]), se1 = smem_u32(&s_e[1][0]);
    const uint32_t st0 = smem_u32(&s_t[0][0]), st1 = smem_u32(&s_t[1][0]);

    if (tid == 0) {
        mbar_init(mb0, 1);
        mbar_init(mb1, 1);
    }
    __syncthreads();
    asm volatile("fence.proxy.async.shared::cta;" ::: "memory");

    // This block's contiguous slice: QPB quads starting at x*QPB.
    const char* ge = (const char*)est + (size_t)b * NPB * 12 + (size_t)x * QPB * 48;
    const char* gt = (const char*)tgt + (size_t)b * NPB * 12 + (size_t)x * QPB * 48;

    // Prologue: fill both buffers.
    if (tid == 0) {
        mbar_expect_tx(mb0, 2 * STAGE_B);
        tma_bulk_1d(se0, ge, STAGE_B, mb0);
        tma_bulk_1d(st0, gt, STAGE_B, mb0);
        mbar_expect_tx(mb1, 2 * STAGE_B);
        tma_bulk_1d(se1, ge + STAGE_B, STAGE_B, mb1);
        tma_bulk_1d(st1, gt + STAGE_B, STAGE_B, mb1);
    }

    u64 acc[9];
#pragma unroll
    for (int q = 0; q < 9; q++) acc[q] = 0ULL;

    for (int i = 0; i < NSTAGES; i++) {
        const int j = i & 1;
        const uint32_t mb = j ? mb1 : mb0;
        mbar_wait(mb, (i >> 1) & 1);

        if (tid < QPS) {
            const float4* be = &s_e[j][3 * tid];
            const float4* bt = &s_t[j][3 * tid];
            accum_chunk(acc, be[0], be[1], be[2], bt[0], bt[1], bt[2]);
        }
        __syncthreads();   // everyone done with buffer j before refill

        if (tid == 0 && i + 2 < NSTAGES) {
            const uint32_t se = j ? se1 : se0;
            const uint32_t st = j ? st1 : st0;
            const size_t off = (size_t)(i + 2) * STAGE_B;
            mbar_expect_tx(mb, 2 * STAGE_B);
            tma_bulk_1d(se, ge + off, STAGE_B, mb);
            tma_bulk_1d(st, gt + off, STAGE_B, mb);
        }
    }

    // Collapse packed halves.
    float a[9];
#pragma unroll
    for (int q = 0; q < 9; q++) {
        float lo, hi;
        unpack2(lo, hi, acc[q]);
        a[q] = lo + hi;
    }

    // Warp reduction.
#pragma unroll
    for (int off = 16; off > 0; off >>= 1) {
#pragma unroll
        for (int q = 0; q < 9; q++)
            a[q] += __shfl_down_sync(0xFFFFFFFFu, a[q], off);
    }

    // Block reduction across 8 warps.
    __shared__ float s_part[NTHR / 32][9];
    const int lane = tid & 31;
    const int warp = tid >> 5;
    if (lane == 0) {
#pragma unroll
        for (int q = 0; q < 9; q++) s_part[warp][q] = a[q];
    }
    __syncthreads();

    if (tid < 9) {
        float s = 0.0f;
#pragma unroll
        for (int w = 0; w < NTHR / 32; w++) s += s_part[w][tid];
        atomicAdd(&g_C[b * 9 + tid], s);
    }

    // ---- hierarchical last-block-done ----
    __shared__ unsigned int s_islast;
    __threadfence();
    if (tid == 0) {
        s_islast = 0;
        if (atomicAdd(&g_cnt_b[b], 1u) == BLKX - 1) {
            __threadfence();
            s_islast = (atomicAdd(&g_cnt, 1u) == BB - 1);
        }
    }
    __syncthreads();
    if (!s_islast) return;

    // ---- finisher: permutation-min epilogue ----
    __shared__ float sC[BB * 9];
    for (int ent = tid; ent < BB * 9; ent += NTHR)
        sC[ent] = __ldcg(&g_C[ent]) * (1.0f / (float)NPB);
    __syncthreads();

    if (tid < 32) {
        const float* c = &sC[tid * 9];
        float best = c[0] + c[4] + c[8];
        best = fminf(best, c[0] + c[7] + c[5]);
        best = fminf(best, c[3] + c[1] + c[8]);
        best = fminf(best, c[3] + c[7] + c[2]);
        best = fminf(best, c[6] + c[1] + c[5]);
        best = fminf(best, c[6] + c[4] + c[2]);
        best *= (1.0f / 3.0f);

#pragma unroll
        for (int off = 16; off > 0; off >>= 1)
            best += __shfl_down_sync(0xFFFFFFFFu, best, off);

        if (tid == 0) out[0] = best * (1.0f / (float)BB);
    }
    __syncthreads();

    // Reset ALL scratch for the next graph replay.
    for (int ent = tid; ent < BB * 9; ent += NTHR) g_C[ent] = 0.0f;
    if (tid < BB) g_cnt_b[tid] = 0u;
    if (tid == 0) g_cnt = 0u;
}

extern "C" void kernel_launch(void* const* d_in, const int* in_sizes, int n_in,
                              void* d_out, int out_size) {
    const float* est = (const float*)d_in[0];
    const float* tgt = (const float*)d_in[1];
    float* out = (float*)d_out;

    pil_tma_kernel<<<NBLK, NTHR>>>(est, tgt, out);
}